// round 2
// baseline (speedup 1.0000x reference)
#include <cuda_runtime.h>
#include <cuda_bf16.h>
#include <cstdint>
#include <math.h>

#define BSZ   8192
#define NINS  5
#define NF    768
#define NH    64
#define NLAY  2
#define NPROJ 320   // 5*64

// ---------------- device scratch (no allocations allowed) ----------------
__device__ __align__(256) float          g_x  [BSZ*NINS*NF];   // fp32 x (layer outputs)
__device__ __align__(256) __nv_bfloat16  g_xb [BSZ*NINS*NF];   // bf16 mirror for MMA
__device__ __align__(256) __nv_bfloat16  g_cb [BSZ*NF];        // claims bf16
__device__ __align__(256) float          g_P  [BSZ*NINS*NPROJ];// key projections
__device__ __align__(256) float          g_own[BSZ*NINS*NH];   // own projections
__device__ __align__(256) float          g_kp [BSZ*NINS*NH];   // agg key proj
__device__ __align__(256) float          g_qp [BSZ*NH];        // agg query proj
__device__ __align__(256) __nv_bfloat16  g_Wa [NLAY*NPROJ*NF]; // W1a packed [l][q*64+h][f]
__device__ __align__(256) __nv_bfloat16  g_Wb [NLAY*NPROJ*NF]; // W1b packed
__device__ __align__(256) __nv_bfloat16  g_aWa[NH*NF];
__device__ __align__(256) __nv_bfloat16  g_aWb[NH*NF];

// ---------------- weight repack + bf16 convert ----------------
__global__ void conv_weights(const float* __restrict__ W1, const float* __restrict__ aggW1) {
    const int NWA = NLAY*NPROJ*NF;                  // 491520
    const int TOT = 2*NWA + 2*NH*NF;
    for (int i = blockIdx.x*blockDim.x + threadIdx.x; i < TOT; i += gridDim.x*blockDim.x) {
        if (i < NWA) {
            int l = i/(NPROJ*NF); int r = (i/NF)%NPROJ; int f = i%NF;
            int q = r>>6, h = r&63;
            g_Wa[i] = __float2bfloat16(W1[(((size_t)(l*NINS+q))*(2*NF) + f)*NH + h]);
        } else if (i < 2*NWA) {
            int j = i-NWA;
            int l = j/(NPROJ*NF); int r = (j/NF)%NPROJ; int f = j%NF;
            int q = r>>6, h = r&63;
            g_Wb[j] = __float2bfloat16(W1[(((size_t)(l*NINS+q))*(2*NF) + NF + f)*NH + h]);
        } else if (i < 2*NWA + NH*NF) {
            int j = i-2*NWA; int h = j/NF; int f = j%NF;
            g_aWa[j] = __float2bfloat16(aggW1[(size_t)f*NH + h]);
        } else {
            int j = i-2*NWA-NH*NF; int h = j/NF; int f = j%NF;
            g_aWb[j] = __float2bfloat16(aggW1[(size_t)(NF+f)*NH + h]);
        }
    }
}

__global__ void conv_inputs(const float4* __restrict__ in4, const float4* __restrict__ cl4) {
    const int NI = BSZ*NINS*NF/4, NC = BSZ*NF/4;
    for (int i = blockIdx.x*blockDim.x + threadIdx.x; i < NI+NC; i += gridDim.x*blockDim.x) {
        float4 v; __nv_bfloat162* dst;
        if (i < NI) { v = in4[i]; dst = (__nv_bfloat162*)g_xb + (size_t)i*2; }
        else        { v = cl4[i-NI]; dst = (__nv_bfloat162*)g_cb + (size_t)(i-NI)*2; }
        __nv_bfloat162 p0, p1;
        p0.x = __float2bfloat16(v.x); p0.y = __float2bfloat16(v.y);
        p1.x = __float2bfloat16(v.z); p1.y = __float2bfloat16(v.w);
        dst[0] = p0; dst[1] = p1;
    }
}

// ---------------- bf16 GEMM via mma.sync (BM=128, BN=64, BK=32) ----------------
__device__ __forceinline__ void cp16(void* smem, const void* g) {
    uint32_t s = (uint32_t)__cvta_generic_to_shared(smem);
    asm volatile("cp.async.cg.shared.global [%0], [%1], 16;\n" :: "r"(s), "l"(g) : "memory");
}

__device__ __forceinline__ void gemm_load_stage(
    __nv_bfloat16 (*As)[40], __nv_bfloat16 (*Bs)[40],
    const __nv_bfloat16* __restrict__ A, const __nv_bfloat16* __restrict__ Bm,
    int rowBase, int rowMul, int rowAdd, int nBase, int kk, int tid)
{
#pragma unroll
    for (int i = 0; i < 2; i++) {
        int ci = tid + i*256;
        int r = ci >> 2, quad = ci & 3;
        const __nv_bfloat16* gp = A + ((size_t)(rowBase+r)*rowMul + rowAdd)*NF + kk + quad*8;
        cp16(&As[r][quad*8], gp);
    }
    {
        int r = tid >> 2, quad = tid & 3;
        const __nv_bfloat16* gp = Bm + (size_t)(nBase+r)*NF + kk + quad*8;
        cp16(&Bs[r][quad*8], gp);
    }
}

// mode 0: key proj  A=g_xb rows=b*5+k, B=g_Wb[l], C=g_P   stride NPROJ, grid(320,5,1)
// mode 1: own proj  A=g_xb rows=b*5+q, B=g_Wa[l]+q*64*NF, C=g_own stride NPROJ, grid(64,1,5)
// mode 2: agg key   A=g_xb rows=b*5+k, B=g_aWb,  C=g_kp   stride NH, grid(320,1,1)
// mode 3: agg query A=g_cb rows=b,     B=g_aWa,  C=g_qp   stride NH, grid(64,1,1)
__global__ void __launch_bounds__(256) gemm_bf16(int mode, int layer)
{
    const __nv_bfloat16* A;
    const __nv_bfloat16* Bm;
    float* C;
    int cRowStride;
    int rowMul = 1, rowAdd = 0, cColAdd = 0;

    if (mode == 0) {
        A = g_xb; Bm = g_Wb + (size_t)layer*NPROJ*NF; C = g_P; cRowStride = NPROJ;
    } else if (mode == 1) {
        int q = blockIdx.z;
        A = g_xb; Bm = g_Wa + (size_t)layer*NPROJ*NF + (size_t)q*64*NF;
        C = g_own; cRowStride = NPROJ;
        rowMul = NINS; rowAdd = q; cColAdd = q*64;
    } else if (mode == 2) {
        A = g_xb; Bm = g_aWb; C = g_kp; cRowStride = NH;
    } else {
        A = g_cb; Bm = g_aWa; C = g_qp; cRowStride = NH;
    }

    __shared__ __nv_bfloat16 As[2][128][40];
    __shared__ __nv_bfloat16 Bs[2][64][40];

    const int tid  = threadIdx.x;
    const int warp = tid >> 5, lane = tid & 31;
    const int wm = warp & 3, wn = warp >> 2;        // 4x2 warps, each 32x32
    const int g  = lane >> 2, t = lane & 3;
    const int rowBase = blockIdx.x * 128;
    const int nBase   = blockIdx.y * 64;

    float acc[2][4][4];
#pragma unroll
    for (int mi=0;mi<2;mi++)
#pragma unroll
        for (int ni=0;ni<4;ni++)
#pragma unroll
            for (int c=0;c<4;c++) acc[mi][ni][c]=0.f;

    gemm_load_stage(As[0], Bs[0], A, Bm, rowBase, rowMul, rowAdd, nBase, 0, tid);
    asm volatile("cp.async.commit_group;\n" ::: "memory");

    const int NK = NF/32;  // 24
    for (int kt = 0; kt < NK; kt++) {
        asm volatile("cp.async.wait_group 0;\n" ::: "memory");
        __syncthreads();
        if (kt + 1 < NK)
            gemm_load_stage(As[(kt+1)&1], Bs[(kt+1)&1], A, Bm, rowBase, rowMul, rowAdd, nBase, (kt+1)*32, tid);
        asm volatile("cp.async.commit_group;\n" ::: "memory");

        const int s = kt & 1;
#pragma unroll
        for (int ks = 0; ks < 32; ks += 16) {
            uint32_t af[2][4], bf[4][2];
#pragma unroll
            for (int mi = 0; mi < 2; mi++) {
                int r0 = wm*32 + mi*16;
                af[mi][0] = *(const uint32_t*)&As[s][r0+g  ][ks+2*t  ];
                af[mi][1] = *(const uint32_t*)&As[s][r0+g+8][ks+2*t  ];
                af[mi][2] = *(const uint32_t*)&As[s][r0+g  ][ks+2*t+8];
                af[mi][3] = *(const uint32_t*)&As[s][r0+g+8][ks+2*t+8];
            }
#pragma unroll
            for (int ni = 0; ni < 4; ni++) {
                int n0 = wn*32 + ni*8 + g;
                bf[ni][0] = *(const uint32_t*)&Bs[s][n0][ks+2*t  ];
                bf[ni][1] = *(const uint32_t*)&Bs[s][n0][ks+2*t+8];
            }
#pragma unroll
            for (int mi = 0; mi < 2; mi++)
#pragma unroll
                for (int ni = 0; ni < 4; ni++) {
                    asm volatile(
                        "mma.sync.aligned.m16n8k16.row.col.f32.bf16.bf16.f32 "
                        "{%0,%1,%2,%3},{%4,%5,%6,%7},{%8,%9},{%0,%1,%2,%3};\n"
                        : "+f"(acc[mi][ni][0]), "+f"(acc[mi][ni][1]),
                          "+f"(acc[mi][ni][2]), "+f"(acc[mi][ni][3])
                        : "r"(af[mi][0]), "r"(af[mi][1]), "r"(af[mi][2]), "r"(af[mi][3]),
                          "r"(bf[ni][0]), "r"(bf[ni][1]));
                }
        }
    }

#pragma unroll
    for (int mi = 0; mi < 2; mi++)
#pragma unroll
        for (int ni = 0; ni < 4; ni++) {
            int r0 = rowBase + wm*32 + mi*16 + g;
            int c0 = nBase + cColAdd + wn*32 + ni*8 + 2*t;
            float2 v0 = make_float2(acc[mi][ni][0], acc[mi][ni][1]);
            float2 v1 = make_float2(acc[mi][ni][2], acc[mi][ni][3]);
            *(float2*)&C[(size_t)r0     * cRowStride + c0] = v0;
            *(float2*)&C[(size_t)(r0+8) * cRowStride + c0] = v1;
        }
}

// ---------------- attention (scores + softmax + weighted sum), fp32 ----------------
__global__ void __launch_bounds__(256) attn_kernel(
    int layer, const float* __restrict__ inputs,
    const float* __restrict__ b1, const float* __restrict__ W2, const float* __restrict__ b2)
{
    const int b = blockIdx.x, tid = threadIdx.x;
    const float* xsrc = (layer == 0) ? inputs : g_x;
    const float* b1l = b1 + layer*NINS*NH;
    const float* W2l = W2 + layer*NINS*NH;
    const float* b2l = b2 + layer*NINS;

    __shared__ float sx[NINS*NF];
    __shared__ float sP[NINS*NPROJ];
    __shared__ float sown[NPROJ], sb1[NPROJ], sW2[NPROJ], sb2[NINS];
    __shared__ float ssc[NINS][NINS], sw[NINS][NINS];

    for (int i = tid; i < NINS*NF;    i += 256) sx[i] = xsrc[(size_t)b*NINS*NF + i];
    for (int i = tid; i < NINS*NPROJ; i += 256) sP[i] = g_P[(size_t)b*NINS*NPROJ + i];
    for (int i = tid; i < NPROJ;      i += 256) {
        sown[i] = g_own[(size_t)b*NPROJ + i];
        sb1[i]  = b1l[i];
        sW2[i]  = W2l[i];
    }
    if (tid < NINS) sb2[tid] = b2l[tid];
    __syncthreads();

    const int warp = tid >> 5, lane = tid & 31;
    for (int pair = warp; pair < 25; pair += 8) {
        int q = pair / 5, k = pair % 5;
        float s = 0.f;
#pragma unroll
        for (int hh = 0; hh < 2; hh++) {
            int h = lane + hh*32;
            float v = sown[q*64+h] + sP[k*NPROJ + q*64 + h] + sb1[q*64+h];
            v = fmaxf(v, 0.f);
            s = fmaf(v, sW2[q*64+h], s);
        }
#pragma unroll
        for (int o = 16; o > 0; o >>= 1) s += __shfl_xor_sync(0xffffffffu, s, o);
        if (lane == 0) ssc[q][k] = s + sb2[q];
    }
    __syncthreads();

    if (tid < NINS) {
        int q = tid;
        float m = -1e30f;
#pragma unroll
        for (int k = 0; k < NINS; k++) m = fmaxf(m, ssc[q][k]);
        float e[NINS], sum = 0.f;
#pragma unroll
        for (int k = 0; k < NINS; k++) { e[k] = expf(ssc[q][k]-m); sum += e[k]; }
        float inv = 1.f/sum;
#pragma unroll
        for (int k = 0; k < NINS; k++) sw[q][k] = e[k]*inv;
    }
    __syncthreads();

    float w[NINS][NINS];
#pragma unroll
    for (int q = 0; q < NINS; q++)
#pragma unroll
        for (int k = 0; k < NINS; k++) w[q][k] = sw[q][k];

    for (int f = tid; f < NF; f += 256) {
        float xk[NINS];
#pragma unroll
        for (int k = 0; k < NINS; k++) xk[k] = sx[k*NF+f];
#pragma unroll
        for (int q = 0; q < NINS; q++) {
            float a = 0.f;
#pragma unroll
            for (int k = 0; k < NINS; k++) a = fmaf(w[q][k], xk[k], a);
            size_t idx = ((size_t)b*NINS + q)*NF + f;
            g_x[idx]  = a;
            g_xb[idx] = __float2bfloat16(a);
        }
    }
}

// ---------------- aggregate + output head, fp32 ----------------
__global__ void __launch_bounds__(256) agg_kernel(
    const float* __restrict__ aggb1, const float* __restrict__ aggW2,
    const float* __restrict__ aggb2, const float* __restrict__ Wout,
    const float* __restrict__ bout,  float* __restrict__ out)
{
    const int b = blockIdx.x, tid = threadIdx.x;
    __shared__ float sx[NINS*NF];
    __shared__ float skp[NINS*NH], sq[NH], sb1[NH], sW2a[NH];
    __shared__ float ssc[NINS], sw[NINS];
    __shared__ float red[3][256];

    for (int i = tid; i < NINS*NF; i += 256) sx[i]  = g_x [(size_t)b*NINS*NF + i];
    for (int i = tid; i < NINS*NH; i += 256) skp[i] = g_kp[(size_t)b*NINS*NH + i];
    for (int i = tid; i < NH;      i += 256) {
        sq[i]   = g_qp[(size_t)b*NH + i];
        sb1[i]  = aggb1[i];
        sW2a[i] = aggW2[i];
    }
    __syncthreads();

    const int warp = tid >> 5, lane = tid & 31;
    if (warp < NINS) {
        int k = warp;
        float s = 0.f;
#pragma unroll
        for (int hh = 0; hh < 2; hh++) {
            int h = lane + hh*32;
            float v = fmaxf(sq[h] + skp[k*NH+h] + sb1[h], 0.f);
            s = fmaf(v, sW2a[h], s);
        }
#pragma unroll
        for (int o = 16; o > 0; o >>= 1) s += __shfl_xor_sync(0xffffffffu, s, o);
        if (lane == 0) ssc[k] = s + aggb2[0];
    }
    __syncthreads();

    if (tid == 0) {
        float m = -1e30f;
#pragma unroll
        for (int k = 0; k < NINS; k++) m = fmaxf(m, ssc[k]);
        float e[NINS], sum = 0.f;
#pragma unroll
        for (int k = 0; k < NINS; k++) { e[k] = expf(ssc[k]-m); sum += e[k]; }
        float inv = 1.f/sum;
#pragma unroll
        for (int k = 0; k < NINS; k++) sw[k] = e[k]*inv;
    }
    __syncthreads();

    float w[NINS];
#pragma unroll
    for (int k = 0; k < NINS; k++) w[k] = sw[k];

    float a0 = 0.f, a1 = 0.f, a2 = 0.f;
    for (int f = tid; f < NF; f += 256) {
        float p = 0.f;
#pragma unroll
        for (int k = 0; k < NINS; k++) p = fmaf(w[k], sx[k*NF+f], p);
        a0 = fmaf(p, Wout[(size_t)f*3+0], a0);
        a1 = fmaf(p, Wout[(size_t)f*3+1], a1);
        a2 = fmaf(p, Wout[(size_t)f*3+2], a2);
    }
    red[0][tid] = a0; red[1][tid] = a1; red[2][tid] = a2;
    __syncthreads();
    for (int s = 128; s > 0; s >>= 1) {
        if (tid < s) {
            red[0][tid] += red[0][tid+s];
            red[1][tid] += red[1][tid+s];
            red[2][tid] += red[2][tid+s];
        }
        __syncthreads();
    }
    if (tid == 0) {
        float l0 = fmaxf(red[0][0] + bout[0], 0.f);
        float l1 = fmaxf(red[1][0] + bout[1], 0.f);
        float l2 = fmaxf(red[2][0] + bout[2], 0.f);
        float m  = fmaxf(l0, fmaxf(l1, l2));
        float lse = m + logf(expf(l0-m) + expf(l1-m) + expf(l2-m));
        out[(size_t)b*3+0] = l0 - lse;
        out[(size_t)b*3+1] = l1 - lse;
        out[(size_t)b*3+2] = l2 - lse;
    }
}

// ---------------- host launch ----------------
extern "C" void kernel_launch(void* const* d_in, const int* in_sizes, int n_in,
                              void* d_out, int out_size)
{
    const float* inputs = (const float*)d_in[0];
    const float* claims = (const float*)d_in[1];
    const float* W1     = (const float*)d_in[2];
    const float* b1     = (const float*)d_in[3];
    const float* W2     = (const float*)d_in[4];
    const float* b2     = (const float*)d_in[5];
    const float* aggW1  = (const float*)d_in[6];
    const float* aggb1  = (const float*)d_in[7];
    const float* aggW2  = (const float*)d_in[8];
    const float* aggb2  = (const float*)d_in[9];
    const float* Wout   = (const float*)d_in[10];
    const float* bout   = (const float*)d_in[11];
    float* out = (float*)d_out;

    conv_weights<<<512, 256>>>(W1, aggW1);
    conv_inputs<<<2048, 256>>>((const float4*)inputs, (const float4*)claims);

    for (int l = 0; l < NLAY; l++) {
        gemm_bf16<<<dim3(320, 5, 1), 256>>>(0, l);   // key projections
        gemm_bf16<<<dim3(64, 1, 5), 256>>>(1, l);    // own projections
        attn_kernel<<<BSZ, 256>>>(l, inputs, b1, W2, b2);
    }

    gemm_bf16<<<dim3(320, 1, 1), 256>>>(2, 0);       // agg key proj
    gemm_bf16<<<dim3(64, 1, 1), 256>>>(3, 0);        // agg query proj

    agg_kernel<<<BSZ, 256>>>(aggb1, aggW2, aggb2, Wout, bout, out);
}

// round 3
// speedup vs baseline: 1.3260x; 1.3260x over previous
#include <cuda_runtime.h>
#include <cuda_bf16.h>
#include <cstdint>
#include <math.h>

#define BSZ   8192
#define NINS  5
#define NF    768
#define NH    64
#define NLAY  2
#define NPROJ 320   // 5*64

// ---------------- device scratch (no allocations allowed) ----------------
__device__ __align__(256) float          g_x  [BSZ*NINS*NF];   // fp32 x (layer outputs)
__device__ __align__(256) __nv_bfloat16  g_xb [BSZ*NINS*NF];   // bf16 mirror for MMA
__device__ __align__(256) __nv_bfloat16  g_cb [BSZ*NF];        // claims bf16
__device__ __align__(256) __nv_bfloat16  g_P  [BSZ*NINS*NPROJ];// key projections (bf16)
__device__ __align__(256) __nv_bfloat16  g_own[BSZ*NPROJ];     // own projections (bf16)
__device__ __align__(256) __nv_bfloat16  g_kp [BSZ*NINS*NH];   // agg key proj (bf16)
__device__ __align__(256) __nv_bfloat16  g_qp [BSZ*NH];        // agg query proj (bf16)
__device__ __align__(256) __nv_bfloat16  g_Wa [NLAY*NPROJ*NF]; // W1a packed [l][q*64+h][f]
__device__ __align__(256) __nv_bfloat16  g_Wb [NLAY*NPROJ*NF]; // W1b packed
__device__ __align__(256) __nv_bfloat16  g_aWa[NH*NF];
__device__ __align__(256) __nv_bfloat16  g_aWb[NH*NF];

// ---------------- weight repack + bf16 convert ----------------
__global__ void conv_weights(const float* __restrict__ W1, const float* __restrict__ aggW1) {
    const int NWA = NLAY*NPROJ*NF;                  // 491520
    const int TOT = 2*NWA + 2*NH*NF;
    for (int i = blockIdx.x*blockDim.x + threadIdx.x; i < TOT; i += gridDim.x*blockDim.x) {
        if (i < NWA) {
            int l = i/(NPROJ*NF); int r = (i/NF)%NPROJ; int f = i%NF;
            int q = r>>6, h = r&63;
            g_Wa[i] = __float2bfloat16(W1[(((size_t)(l*NINS+q))*(2*NF) + f)*NH + h]);
        } else if (i < 2*NWA) {
            int j = i-NWA;
            int l = j/(NPROJ*NF); int r = (j/NF)%NPROJ; int f = j%NF;
            int q = r>>6, h = r&63;
            g_Wb[j] = __float2bfloat16(W1[(((size_t)(l*NINS+q))*(2*NF) + NF + f)*NH + h]);
        } else if (i < 2*NWA + NH*NF) {
            int j = i-2*NWA; int h = j/NF; int f = j%NF;
            g_aWa[j] = __float2bfloat16(aggW1[(size_t)f*NH + h]);
        } else {
            int j = i-2*NWA-NH*NF; int h = j/NF; int f = j%NF;
            g_aWb[j] = __float2bfloat16(aggW1[(size_t)(NF+f)*NH + h]);
        }
    }
}

__global__ void conv_inputs(const float4* __restrict__ in4, const float4* __restrict__ cl4) {
    const int NI = BSZ*NINS*NF/4, NC = BSZ*NF/4;
    for (int i = blockIdx.x*blockDim.x + threadIdx.x; i < NI+NC; i += gridDim.x*blockDim.x) {
        float4 v; __nv_bfloat162* dst;
        if (i < NI) { v = in4[i]; dst = (__nv_bfloat162*)g_xb + (size_t)i*2; }
        else        { v = cl4[i-NI]; dst = (__nv_bfloat162*)g_cb + (size_t)(i-NI)*2; }
        __nv_bfloat162 p0, p1;
        p0.x = __float2bfloat16(v.x); p0.y = __float2bfloat16(v.y);
        p1.x = __float2bfloat16(v.z); p1.y = __float2bfloat16(v.w);
        dst[0] = p0; dst[1] = p1;
    }
}

// ---------------- bf16 GEMM via mma.sync (BM=128, BN=64, BK=32, 3-stage) ----------------
__device__ __forceinline__ void cp16(void* smem, const void* g) {
    uint32_t s = (uint32_t)__cvta_generic_to_shared(smem);
    asm volatile("cp.async.cg.shared.global [%0], [%1], 16;\n" :: "r"(s), "l"(g) : "memory");
}

__device__ __forceinline__ void gemm_load_stage(
    __nv_bfloat16 (*As)[40], __nv_bfloat16 (*Bs)[40],
    const __nv_bfloat16* __restrict__ A, const __nv_bfloat16* __restrict__ Bm,
    int rowBase, int rowMul, int rowAdd, int nBase, int kk, int tid)
{
#pragma unroll
    for (int i = 0; i < 2; i++) {
        int ci = tid + i*256;
        int r = ci >> 2, quad = ci & 3;
        const __nv_bfloat16* gp = A + ((size_t)(rowBase+r)*rowMul + rowAdd)*NF + kk + quad*8;
        cp16(&As[r][quad*8], gp);
    }
    {
        int r = tid >> 2, quad = tid & 3;
        const __nv_bfloat16* gp = Bm + (size_t)(nBase+r)*NF + kk + quad*8;
        cp16(&Bs[r][quad*8], gp);
    }
}

// mode 0: key proj  A=g_xb rows=b*5+k, B=g_Wb[l], C=g_P   stride NPROJ, grid(5,320)   [N-tile fastest -> L2 reuse of A]
// mode 1: own proj  A=g_xb rows=b*5+q, B=g_Wa[l]+q*64*NF, C=g_own stride NPROJ, grid(64,1,5)
// mode 2: agg key   A=g_xb rows=b*5+k, B=g_aWb,  C=g_kp   stride NH, grid(320,1,1)
// mode 3: agg query A=g_cb rows=b,     B=g_aWa,  C=g_qp   stride NH, grid(64,1,1)
__global__ void __launch_bounds__(256) gemm_bf16(int mode, int layer)
{
    const __nv_bfloat16* A;
    const __nv_bfloat16* Bm;
    __nv_bfloat16* C;
    int cRowStride;
    int rowMul = 1, rowAdd = 0, cColAdd = 0;
    int rowBase, nBase;

    if (mode == 0) {
        A = g_xb; Bm = g_Wb + (size_t)layer*NPROJ*NF; C = g_P; cRowStride = NPROJ;
        nBase   = blockIdx.x * 64;      // N-tile fastest: 5 sibling blocks share A tile via L2
        rowBase = blockIdx.y * 128;
    } else if (mode == 1) {
        int q = blockIdx.z;
        A = g_xb; Bm = g_Wa + (size_t)layer*NPROJ*NF + (size_t)q*64*NF;
        C = g_own; cRowStride = NPROJ;
        rowMul = NINS; rowAdd = q; cColAdd = q*64;
        rowBase = blockIdx.x * 128; nBase = 0;
    } else if (mode == 2) {
        A = g_xb; Bm = g_aWb; C = g_kp; cRowStride = NH;
        rowBase = blockIdx.x * 128; nBase = 0;
    } else {
        A = g_cb; Bm = g_aWa; C = g_qp; cRowStride = NH;
        rowBase = blockIdx.x * 128; nBase = 0;
    }

    __shared__ __nv_bfloat16 As[3][128][40];
    __shared__ __nv_bfloat16 Bs[3][64][40];

    const int tid  = threadIdx.x;
    const int warp = tid >> 5, lane = tid & 31;
    const int wm = warp & 3, wn = warp >> 2;        // 4x2 warps, each 32x32
    const int g  = lane >> 2, t = lane & 3;

    float acc[2][4][4];
#pragma unroll
    for (int mi=0;mi<2;mi++)
#pragma unroll
        for (int ni=0;ni<4;ni++)
#pragma unroll
            for (int c=0;c<4;c++) acc[mi][ni][c]=0.f;

    const int NK = NF/32;  // 24
    gemm_load_stage(As[0], Bs[0], A, Bm, rowBase, rowMul, rowAdd, nBase, 0, tid);
    asm volatile("cp.async.commit_group;\n" ::: "memory");
    gemm_load_stage(As[1], Bs[1], A, Bm, rowBase, rowMul, rowAdd, nBase, 32, tid);
    asm volatile("cp.async.commit_group;\n" ::: "memory");

    for (int kt = 0; kt < NK; kt++) {
        if (kt < NK-1) { asm volatile("cp.async.wait_group 1;\n" ::: "memory"); }
        else           { asm volatile("cp.async.wait_group 0;\n" ::: "memory"); }
        __syncthreads();
        if (kt + 2 < NK) {
            int st = (kt+2)%3;
            gemm_load_stage(As[st], Bs[st], A, Bm, rowBase, rowMul, rowAdd, nBase, (kt+2)*32, tid);
            asm volatile("cp.async.commit_group;\n" ::: "memory");
        }

        const int s = kt % 3;
#pragma unroll
        for (int ks = 0; ks < 32; ks += 16) {
            uint32_t af[2][4], bf[4][2];
#pragma unroll
            for (int mi = 0; mi < 2; mi++) {
                int r0 = wm*32 + mi*16;
                af[mi][0] = *(const uint32_t*)&As[s][r0+g  ][ks+2*t  ];
                af[mi][1] = *(const uint32_t*)&As[s][r0+g+8][ks+2*t  ];
                af[mi][2] = *(const uint32_t*)&As[s][r0+g  ][ks+2*t+8];
                af[mi][3] = *(const uint32_t*)&As[s][r0+g+8][ks+2*t+8];
            }
#pragma unroll
            for (int ni = 0; ni < 4; ni++) {
                int n0 = wn*32 + ni*8 + g;
                bf[ni][0] = *(const uint32_t*)&Bs[s][n0][ks+2*t  ];
                bf[ni][1] = *(const uint32_t*)&Bs[s][n0][ks+2*t+8];
            }
#pragma unroll
            for (int mi = 0; mi < 2; mi++)
#pragma unroll
                for (int ni = 0; ni < 4; ni++) {
                    asm volatile(
                        "mma.sync.aligned.m16n8k16.row.col.f32.bf16.bf16.f32 "
                        "{%0,%1,%2,%3},{%4,%5,%6,%7},{%8,%9},{%0,%1,%2,%3};\n"
                        : "+f"(acc[mi][ni][0]), "+f"(acc[mi][ni][1]),
                          "+f"(acc[mi][ni][2]), "+f"(acc[mi][ni][3])
                        : "r"(af[mi][0]), "r"(af[mi][1]), "r"(af[mi][2]), "r"(af[mi][3]),
                          "r"(bf[ni][0]), "r"(bf[ni][1]));
                }
        }
    }

#pragma unroll
    for (int mi = 0; mi < 2; mi++)
#pragma unroll
        for (int ni = 0; ni < 4; ni++) {
            int r0 = rowBase + wm*32 + mi*16 + g;
            int c0 = nBase + cColAdd + wn*32 + ni*8 + 2*t;
            __nv_bfloat162 v0, v1;
            v0.x = __float2bfloat16(acc[mi][ni][0]); v0.y = __float2bfloat16(acc[mi][ni][1]);
            v1.x = __float2bfloat16(acc[mi][ni][2]); v1.y = __float2bfloat16(acc[mi][ni][3]);
            *(__nv_bfloat162*)&C[(size_t)r0     * cRowStride + c0] = v0;
            *(__nv_bfloat162*)&C[(size_t)(r0+8) * cRowStride + c0] = v1;
        }
}

// ---------------- attention (scores + softmax + weighted sum), fp32 ----------------
__global__ void __launch_bounds__(256) attn_kernel(
    int layer, const float* __restrict__ inputs,
    const float* __restrict__ b1, const float* __restrict__ W2, const float* __restrict__ b2)
{
    const int b = blockIdx.x, tid = threadIdx.x;
    const float* xsrc = (layer == 0) ? inputs : g_x;
    const float* b1l = b1 + layer*NINS*NH;
    const float* W2l = W2 + layer*NINS*NH;
    const float* b2l = b2 + layer*NINS;

    __shared__ float sx[NINS*NF];
    __shared__ float sP[NINS*NPROJ];
    __shared__ float sown[NPROJ], sb1[NPROJ], sW2[NPROJ], sb2[NINS];
    __shared__ float ssc[NINS][NINS], sw[NINS][NINS];

    {   // vectorized loads
        const float4* xs4 = (const float4*)(xsrc + (size_t)b*NINS*NF);
        for (int i = tid; i < NINS*NF/4; i += 256) ((float4*)sx)[i] = xs4[i];
        const __nv_bfloat162* Pp = (const __nv_bfloat162*)(g_P + (size_t)b*NINS*NPROJ);
        for (int i = tid; i < NINS*NPROJ/2; i += 256) {
            float2 f = __bfloat1622float2(Pp[i]);
            sP[2*i] = f.x; sP[2*i+1] = f.y;
        }
        const __nv_bfloat162* Op = (const __nv_bfloat162*)(g_own + (size_t)b*NPROJ);
        for (int i = tid; i < NPROJ/2; i += 256) {
            float2 f = __bfloat1622float2(Op[i]);
            sown[2*i] = f.x; sown[2*i+1] = f.y;
        }
        for (int i = tid; i < NPROJ; i += 256) { sb1[i] = b1l[i]; sW2[i] = W2l[i]; }
        if (tid < NINS) sb2[tid] = b2l[tid];
    }
    __syncthreads();

    const int warp = tid >> 5, lane = tid & 31;
    for (int pair = warp; pair < 25; pair += 8) {
        int q = pair / 5, k = pair % 5;
        float s = 0.f;
#pragma unroll
        for (int hh = 0; hh < 2; hh++) {
            int h = lane + hh*32;
            float v = sown[q*64+h] + sP[k*NPROJ + q*64 + h] + sb1[q*64+h];
            v = fmaxf(v, 0.f);
            s = fmaf(v, sW2[q*64+h], s);
        }
#pragma unroll
        for (int o = 16; o > 0; o >>= 1) s += __shfl_xor_sync(0xffffffffu, s, o);
        if (lane == 0) ssc[q][k] = s + sb2[q];
    }
    __syncthreads();

    if (tid < NINS) {
        int q = tid;
        float m = -1e30f;
#pragma unroll
        for (int k = 0; k < NINS; k++) m = fmaxf(m, ssc[q][k]);
        float e[NINS], sum = 0.f;
#pragma unroll
        for (int k = 0; k < NINS; k++) { e[k] = expf(ssc[q][k]-m); sum += e[k]; }
        float inv = 1.f/sum;
#pragma unroll
        for (int k = 0; k < NINS; k++) sw[q][k] = e[k]*inv;
    }
    __syncthreads();

    float w[NINS][NINS];
#pragma unroll
    for (int q = 0; q < NINS; q++)
#pragma unroll
        for (int k = 0; k < NINS; k++) w[q][k] = sw[q][k];

    // pairwise f so bf16 stores are 4B
    for (int p = tid; p < NF/2; p += 256) {
        int f = 2*p;
        float xk0[NINS], xk1[NINS];
#pragma unroll
        for (int k = 0; k < NINS; k++) { xk0[k] = sx[k*NF+f]; xk1[k] = sx[k*NF+f+1]; }
#pragma unroll
        for (int q = 0; q < NINS; q++) {
            float a0 = 0.f, a1 = 0.f;
#pragma unroll
            for (int k = 0; k < NINS; k++) {
                a0 = fmaf(w[q][k], xk0[k], a0);
                a1 = fmaf(w[q][k], xk1[k], a1);
            }
            size_t idx = ((size_t)b*NINS + q)*NF + f;
            *(float2*)&g_x[idx] = make_float2(a0, a1);
            __nv_bfloat162 bb; bb.x = __float2bfloat16(a0); bb.y = __float2bfloat16(a1);
            *(__nv_bfloat162*)&g_xb[idx] = bb;
        }
    }
}

// ---------------- aggregate + output head, fp32 ----------------
__global__ void __launch_bounds__(256) agg_kernel(
    const float* __restrict__ aggb1, const float* __restrict__ aggW2,
    const float* __restrict__ aggb2, const float* __restrict__ Wout,
    const float* __restrict__ bout,  float* __restrict__ out)
{
    const int b = blockIdx.x, tid = threadIdx.x;
    __shared__ float sx[NINS*NF];
    __shared__ float skp[NINS*NH], sq[NH], sb1[NH], sW2a[NH];
    __shared__ float ssc[NINS], sw[NINS];
    __shared__ float red[3][256];

    {
        const float4* xs4 = (const float4*)(g_x + (size_t)b*NINS*NF);
        for (int i = tid; i < NINS*NF/4; i += 256) ((float4*)sx)[i] = xs4[i];
        const __nv_bfloat162* kpp = (const __nv_bfloat162*)(g_kp + (size_t)b*NINS*NH);
        for (int i = tid; i < NINS*NH/2; i += 256) {
            float2 f = __bfloat1622float2(kpp[i]);
            skp[2*i] = f.x; skp[2*i+1] = f.y;
        }
        const __nv_bfloat162* qpp = (const __nv_bfloat162*)(g_qp + (size_t)b*NH);
        for (int i = tid; i < NH/2; i += 256) {
            float2 f = __bfloat1622float2(qpp[i]);
            sq[2*i] = f.x; sq[2*i+1] = f.y;
        }
        for (int i = tid; i < NH; i += 256) { sb1[i] = aggb1[i]; sW2a[i] = aggW2[i]; }
    }
    __syncthreads();

    const int warp = tid >> 5, lane = tid & 31;
    if (warp < NINS) {
        int k = warp;
        float s = 0.f;
#pragma unroll
        for (int hh = 0; hh < 2; hh++) {
            int h = lane + hh*32;
            float v = fmaxf(sq[h] + skp[k*NH+h] + sb1[h], 0.f);
            s = fmaf(v, sW2a[h], s);
        }
#pragma unroll
        for (int o = 16; o > 0; o >>= 1) s += __shfl_xor_sync(0xffffffffu, s, o);
        if (lane == 0) ssc[k] = s + aggb2[0];
    }
    __syncthreads();

    if (tid == 0) {
        float m = -1e30f;
#pragma unroll
        for (int k = 0; k < NINS; k++) m = fmaxf(m, ssc[k]);
        float e[NINS], sum = 0.f;
#pragma unroll
        for (int k = 0; k < NINS; k++) { e[k] = expf(ssc[k]-m); sum += e[k]; }
        float inv = 1.f/sum;
#pragma unroll
        for (int k = 0; k < NINS; k++) sw[k] = e[k]*inv;
    }
    __syncthreads();

    float w[NINS];
#pragma unroll
    for (int k = 0; k < NINS; k++) w[k] = sw[k];

    float a0 = 0.f, a1 = 0.f, a2 = 0.f;
    for (int f = tid; f < NF; f += 256) {
        float p = 0.f;
#pragma unroll
        for (int k = 0; k < NINS; k++) p = fmaf(w[k], sx[k*NF+f], p);
        a0 = fmaf(p, Wout[(size_t)f*3+0], a0);
        a1 = fmaf(p, Wout[(size_t)f*3+1], a1);
        a2 = fmaf(p, Wout[(size_t)f*3+2], a2);
    }
    red[0][tid] = a0; red[1][tid] = a1; red[2][tid] = a2;
    __syncthreads();
    for (int s = 128; s > 0; s >>= 1) {
        if (tid < s) {
            red[0][tid] += red[0][tid+s];
            red[1][tid] += red[1][tid+s];
            red[2][tid] += red[2][tid+s];
        }
        __syncthreads();
    }
    if (tid == 0) {
        float l0 = fmaxf(red[0][0] + bout[0], 0.f);
        float l1 = fmaxf(red[1][0] + bout[1], 0.f);
        float l2 = fmaxf(red[2][0] + bout[2], 0.f);
        float m  = fmaxf(l0, fmaxf(l1, l2));
        float lse = m + logf(expf(l0-m) + expf(l1-m) + expf(l2-m));
        out[(size_t)b*3+0] = l0 - lse;
        out[(size_t)b*3+1] = l1 - lse;
        out[(size_t)b*3+2] = l2 - lse;
    }
}

// ---------------- host launch ----------------
extern "C" void kernel_launch(void* const* d_in, const int* in_sizes, int n_in,
                              void* d_out, int out_size)
{
    const float* inputs = (const float*)d_in[0];
    const float* claims = (const float*)d_in[1];
    const float* W1     = (const float*)d_in[2];
    const float* b1     = (const float*)d_in[3];
    const float* W2     = (const float*)d_in[4];
    const float* b2     = (const float*)d_in[5];
    const float* aggW1  = (const float*)d_in[6];
    const float* aggb1  = (const float*)d_in[7];
    const float* aggW2  = (const float*)d_in[8];
    const float* aggb2  = (const float*)d_in[9];
    const float* Wout   = (const float*)d_in[10];
    const float* bout   = (const float*)d_in[11];
    float* out = (float*)d_out;

    conv_weights<<<512, 256>>>(W1, aggW1);
    conv_inputs<<<2048, 256>>>((const float4*)inputs, (const float4*)claims);

    for (int l = 0; l < NLAY; l++) {
        gemm_bf16<<<dim3(5, 320, 1), 256>>>(0, l);   // key projections (N-tile fastest)
        gemm_bf16<<<dim3(64, 1, 5), 256>>>(1, l);    // own projections
        attn_kernel<<<BSZ, 256>>>(l, inputs, b1, W2, b2);
    }

    gemm_bf16<<<dim3(320, 1, 1), 256>>>(2, 0);       // agg key proj
    gemm_bf16<<<dim3(64, 1, 1), 256>>>(3, 0);        // agg query proj

    agg_kernel<<<BSZ, 256>>>(aggb1, aggW2, aggb2, Wout, bout, out);
}